// round 2
// baseline (speedup 1.0000x reference)
#include <cuda_runtime.h>
#include <math_constants.h>

// Problem constants
#define BSZ   2
#define SEQ   2048
#define HID   2048
#define NHEAD 32
#define HD    16
#define PROJ  512
#define MROWS (BSZ * SEQ)   // 4096
#define SCALE 0.125f        // (2048/8/4)^-0.5

// Scratch (device globals — no allocation allowed)
__device__ float g_QH[MROWS * PROJ];
__device__ float g_KH[MROWS * PROJ];
__device__ float g_VH[MROWS * PROJ];
__device__ float g_AO[MROWS * PROJ];

// ---------------------------------------------------------------------------
// Tiled SGEMM body: C[M=4096, N] = A[4096, K] * W[N, K]^T
// 64x64 tile, TK=16, 256 threads, 4x4 accumulators per thread.
// ---------------------------------------------------------------------------
__device__ __forceinline__ void gemm_nt_body(const float* __restrict__ A,
                                             const float* __restrict__ W,
                                             float* __restrict__ C,
                                             int K, int N) {
    __shared__ float As[16][68];   // [k][m], stride 68 -> conflict-light, 16B aligned rows
    __shared__ float Bs[16][68];   // [k][n]

    const int tid = threadIdx.x;          // 0..255
    const int tx  = tid & 15;             // 0..15 (n direction)
    const int ty  = tid >> 4;             // 0..15 (m direction)
    const int m0  = blockIdx.y * 64;
    const int n0  = blockIdx.x * 64;

    const int lr = tid >> 2;              // 0..63: row within tile
    const int lc = (tid & 3) << 2;        // 0,4,8,12: k offset

    const float* Ap = A + (size_t)(m0 + lr) * K + lc;
    const float* Wp = W + (size_t)(n0 + lr) * K + lc;

    float acc[4][4];
#pragma unroll
    for (int i = 0; i < 4; i++)
#pragma unroll
        for (int j = 0; j < 4; j++) acc[i][j] = 0.f;

    for (int k0 = 0; k0 < K; k0 += 16) {
        float4 av = *(const float4*)(Ap + k0);
        float4 wv = *(const float4*)(Wp + k0);
        As[lc + 0][lr] = av.x; As[lc + 1][lr] = av.y;
        As[lc + 2][lr] = av.z; As[lc + 3][lr] = av.w;
        Bs[lc + 0][lr] = wv.x; Bs[lc + 1][lr] = wv.y;
        Bs[lc + 2][lr] = wv.z; Bs[lc + 3][lr] = wv.w;
        __syncthreads();

#pragma unroll
        for (int kk = 0; kk < 16; kk++) {
            float4 a = *(const float4*)&As[kk][ty << 2];
            float4 b = *(const float4*)&Bs[kk][tx << 2];
            acc[0][0] += a.x * b.x; acc[0][1] += a.x * b.y;
            acc[0][2] += a.x * b.z; acc[0][3] += a.x * b.w;
            acc[1][0] += a.y * b.x; acc[1][1] += a.y * b.y;
            acc[1][2] += a.y * b.z; acc[1][3] += a.y * b.w;
            acc[2][0] += a.z * b.x; acc[2][1] += a.z * b.y;
            acc[2][2] += a.z * b.z; acc[2][3] += a.z * b.w;
            acc[3][0] += a.w * b.x; acc[3][1] += a.w * b.y;
            acc[3][2] += a.w * b.z; acc[3][3] += a.w * b.w;
        }
        __syncthreads();
    }

#pragma unroll
    for (int i = 0; i < 4; i++) {
        float4 r = make_float4(acc[i][0], acc[i][1], acc[i][2], acc[i][3]);
        *(float4*)&C[(size_t)(m0 + (ty << 2) + i) * N + n0 + (tx << 2)] = r;
    }
}

// Projections: z=0 -> QH, z=1 -> KH, z=2 -> VH.   C = X @ W^T  (4096x512, K=2048)
__global__ __launch_bounds__(256) void proj_gemm_kernel(
    const float* __restrict__ q, const float* __restrict__ k, const float* __restrict__ v,
    const float* __restrict__ Wq, const float* __restrict__ Wk, const float* __restrict__ Wv) {
    const float* A;
    const float* W;
    float* C;
    if (blockIdx.z == 0)      { A = q; W = Wq; C = g_QH; }
    else if (blockIdx.z == 1) { A = k; W = Wk; C = g_KH; }
    else                      { A = v; W = Wv; C = g_VH; }
    gemm_nt_body(A, W, C, HID, PROJ);
}

// Output projection: out = AO @ Wo^T   (4096x2048, K=512)
__global__ __launch_bounds__(256) void out_gemm_kernel(
    const float* __restrict__ Wo, float* __restrict__ out) {
    gemm_nt_body(g_AO, Wo, out, PROJ, HID);
}

// ---------------------------------------------------------------------------
// Flash attention: one block = (128 query rows, one head, one batch).
// One thread = one query row. Online softmax in registers, 128-key smem tiles.
// ---------------------------------------------------------------------------
__global__ __launch_bounds__(128) void attn_kernel() {
    __shared__ float4 Ks[128][4];   // [key][d/4]
    __shared__ float4 Vs[128][4];

    const int t = threadIdx.x;                  // 0..127
    const int h = blockIdx.y;
    const int b = blockIdx.z;
    const int s = blockIdx.x * 128 + t;

    const float* qp = g_QH + ((size_t)(b * SEQ + s) * PROJ + h * HD);
    float4 q0 = ((const float4*)qp)[0];
    float4 q1 = ((const float4*)qp)[1];
    float4 q2 = ((const float4*)qp)[2];
    float4 q3 = ((const float4*)qp)[3];
    q0.x *= SCALE; q0.y *= SCALE; q0.z *= SCALE; q0.w *= SCALE;
    q1.x *= SCALE; q1.y *= SCALE; q1.z *= SCALE; q1.w *= SCALE;
    q2.x *= SCALE; q2.y *= SCALE; q2.z *= SCALE; q2.w *= SCALE;
    q3.x *= SCALE; q3.y *= SCALE; q3.z *= SCALE; q3.w *= SCALE;

    float m = -CUDART_INF_F;
    float l = 0.f;
    float o[16];
#pragma unroll
    for (int d = 0; d < 16; d++) o[d] = 0.f;

    const float* kbase = g_KH + ((size_t)b * SEQ * PROJ + h * HD);
    const float* vbase = g_VH + ((size_t)b * SEQ * PROJ + h * HD);

    for (int kt = 0; kt < SEQ; kt += 128) {
        __syncthreads();   // protect smem reuse from previous tile
        const float4* kp = (const float4*)(kbase + (size_t)(kt + t) * PROJ);
        const float4* vp = (const float4*)(vbase + (size_t)(kt + t) * PROJ);
        Ks[t][0] = kp[0]; Ks[t][1] = kp[1]; Ks[t][2] = kp[2]; Ks[t][3] = kp[3];
        Vs[t][0] = vp[0]; Vs[t][1] = vp[1]; Vs[t][2] = vp[2]; Vs[t][3] = vp[3];
        __syncthreads();

        for (int c = 0; c < 128; c += 16) {
            float sc[16];
#pragma unroll
            for (int j = 0; j < 16; j++) {
                float4 k0 = Ks[c + j][0];
                float4 k1 = Ks[c + j][1];
                float4 k2 = Ks[c + j][2];
                float4 k3 = Ks[c + j][3];
                sc[j] = q0.x * k0.x + q0.y * k0.y + q0.z * k0.z + q0.w * k0.w
                      + q1.x * k1.x + q1.y * k1.y + q1.z * k1.z + q1.w * k1.w
                      + q2.x * k2.x + q2.y * k2.y + q2.z * k2.z + q2.w * k2.w
                      + q3.x * k3.x + q3.y * k3.y + q3.z * k3.z + q3.w * k3.w;
            }
            float mc = sc[0];
#pragma unroll
            for (int j = 1; j < 16; j++) mc = fmaxf(mc, sc[j]);
            float mnew = fmaxf(m, mc);
            float alpha = __expf(m - mnew);
            l *= alpha;
#pragma unroll
            for (int d = 0; d < 16; d++) o[d] *= alpha;

#pragma unroll
            for (int j = 0; j < 16; j++) {
                float p = __expf(sc[j] - mnew);
                l += p;
                float4 v0 = Vs[c + j][0];
                float4 v1 = Vs[c + j][1];
                float4 v2 = Vs[c + j][2];
                float4 v3 = Vs[c + j][3];
                o[0]  += p * v0.x; o[1]  += p * v0.y; o[2]  += p * v0.z; o[3]  += p * v0.w;
                o[4]  += p * v1.x; o[5]  += p * v1.y; o[6]  += p * v1.z; o[7]  += p * v1.w;
                o[8]  += p * v2.x; o[9]  += p * v2.y; o[10] += p * v2.z; o[11] += p * v2.w;
                o[12] += p * v3.x; o[13] += p * v3.y; o[14] += p * v3.z; o[15] += p * v3.w;
            }
            m = mnew;
        }
    }

    const float inv = 1.f / l;
    float* op = g_AO + ((size_t)(b * SEQ + s) * PROJ + h * HD);
    ((float4*)op)[0] = make_float4(o[0]  * inv, o[1]  * inv, o[2]  * inv, o[3]  * inv);
    ((float4*)op)[1] = make_float4(o[4]  * inv, o[5]  * inv, o[6]  * inv, o[7]  * inv);
    ((float4*)op)[2] = make_float4(o[8]  * inv, o[9]  * inv, o[10] * inv, o[11] * inv);
    ((float4*)op)[3] = make_float4(o[12] * inv, o[13] * inv, o[14] * inv, o[15] * inv);
}

// ---------------------------------------------------------------------------
extern "C" void kernel_launch(void* const* d_in, const int* in_sizes, int n_in,
                              void* d_out, int out_size) {
    const float* q  = (const float*)d_in[0];
    const float* k  = (const float*)d_in[1];
    const float* v  = (const float*)d_in[2];
    const float* Wq = (const float*)d_in[3];
    const float* Wk = (const float*)d_in[4];
    const float* Wv = (const float*)d_in[5];
    const float* Wo = (const float*)d_in[6];
    float* out = (float*)d_out;

    // 1) Q/K/V projections: 4096x512, K=2048, fused over gridDim.z
    {
        dim3 grid(PROJ / 64, MROWS / 64, 3);
        proj_gemm_kernel<<<grid, 256>>>(q, k, v, Wq, Wk, Wv);
    }
    // 2) Attention (flash-style)
    {
        dim3 grid(SEQ / 128, NHEAD, BSZ);
        attn_kernel<<<grid, 128>>>();
    }
    // 3) Output projection: 4096x2048, K=512
    {
        dim3 grid(HID / 64, MROWS / 64);
        out_gemm_kernel<<<grid, 256>>>(Wo, out);
    }
}

// round 4
// speedup vs baseline: 1.3925x; 1.3925x over previous
#include <cuda_runtime.h>
#include <cuda_bf16.h>
#include <math_constants.h>
#include <cstdint>

// Problem constants
#define BSZ   2
#define SEQ   2048
#define HID   2048
#define NHEAD 32
#define HD    16
#define PROJ  512
#define MROWS (BSZ * SEQ)   // 4096
#define SCALE 0.125f        // (2048/8/4)^-0.5

// Scratch (device globals — no allocation allowed)
__device__ float g_QH[MROWS * PROJ];
__device__ float g_KH[MROWS * PROJ];
__device__ float g_VH[MROWS * PROJ];
__device__ float g_AO[MROWS * PROJ];

// ===========================================================================
// Split-bf16 tensor-core GEMM:  C[M,N] = A[M,K] @ W[N,K]^T
// x = hi + lo (bf16 each); C = Ahi*Whi + Ahi*Wlo + Alo*Whi  (error ~2^-18)
// CTA tile 128x128, K-chunk 32, 8 warps (warp tile 64x32), mma.m16n8k16.bf16
// ===========================================================================

#define GBM 128
#define GBN 128
#define GBK 32
#define SKB 36          // bf16 row stride in smem (32 data + 4 pad)
#define GTHREADS 256

__device__ __forceinline__ void mma_bf16(float* c, const uint32_t* a, const uint32_t* b) {
    asm volatile(
        "mma.sync.aligned.m16n8k16.row.col.f32.bf16.bf16.f32 "
        "{%0,%1,%2,%3}, {%4,%5,%6,%7}, {%8,%9}, {%0,%1,%2,%3};"
        : "+f"(c[0]), "+f"(c[1]), "+f"(c[2]), "+f"(c[3])
        : "r"(a[0]), "r"(a[1]), "r"(a[2]), "r"(a[3]), "r"(b[0]), "r"(b[1]));
}

// split float -> (hi, lo) bf16 pair
__device__ __forceinline__ void split2(float x, float y, uint32_t& hi, uint32_t& lo) {
    __nv_bfloat16 hx = __float2bfloat16_rn(x);
    __nv_bfloat16 hy = __float2bfloat16_rn(y);
    float rx = x - __bfloat162float(hx);
    float ry = y - __bfloat162float(hy);
    __nv_bfloat16 lx = __float2bfloat16_rn(rx);
    __nv_bfloat16 ly = __float2bfloat16_rn(ry);
    hi = (uint32_t)__bfloat16_as_ushort(hx) | ((uint32_t)__bfloat16_as_ushort(hy) << 16);
    lo = (uint32_t)__bfloat16_as_ushort(lx) | ((uint32_t)__bfloat16_as_ushort(ly) << 16);
}

__device__ __forceinline__ void tc_gemm_body(const float* __restrict__ A,
                                             const float* __restrict__ W,
                                             float* __restrict__ C,
                                             int K, int N) {
    __shared__ __nv_bfloat16 Ah[GBM][SKB];
    __shared__ __nv_bfloat16 Al[GBM][SKB];
    __shared__ __nv_bfloat16 Bh[GBN][SKB];
    __shared__ __nv_bfloat16 Bl[GBN][SKB];

    const int tid = threadIdx.x;
    const int wid = tid >> 5;
    const int lane = tid & 31;
    const int wm = wid >> 2;          // 0..1 -> 64-row half
    const int wn = wid & 3;           // 0..3 -> 32-col quarter
    const int gid = lane >> 2;        // 0..7
    const int tig = lane & 3;         // 0..3

    const int m0 = blockIdx.y * GBM;
    const int n0 = blockIdx.x * GBN;
    const int nc = K / GBK;

    float acc[4][4][4];
#pragma unroll
    for (int mt = 0; mt < 4; mt++)
#pragma unroll
        for (int nt = 0; nt < 4; nt++)
#pragma unroll
            for (int r = 0; r < 4; r++) acc[mt][nt][r] = 0.f;

    for (int i = 0; i < nc; i++) {
        const int k0 = i * GBK;
        __syncthreads();
        // Stage: 128x32 floats each for A and B -> hi/lo bf16 tiles.
        // 1024 float4 per tile, 4 per thread.
#pragma unroll
        for (int t = 0; t < 4; t++) {
            const int f = tid + t * GTHREADS;
            const int row = f >> 3;
            const int c4 = (f & 7) * 4;
            float4 av = *(const float4*)(A + (size_t)(m0 + row) * K + k0 + c4);
            float4 wv = *(const float4*)(W + (size_t)(n0 + row) * K + k0 + c4);
            uint32_t h01, l01, h23, l23;
            split2(av.x, av.y, h01, l01);
            split2(av.z, av.w, h23, l23);
            *(uint32_t*)&Ah[row][c4]     = h01;
            *(uint32_t*)&Ah[row][c4 + 2] = h23;
            *(uint32_t*)&Al[row][c4]     = l01;
            *(uint32_t*)&Al[row][c4 + 2] = l23;
            split2(wv.x, wv.y, h01, l01);
            split2(wv.z, wv.w, h23, l23);
            *(uint32_t*)&Bh[row][c4]     = h01;
            *(uint32_t*)&Bh[row][c4 + 2] = h23;
            *(uint32_t*)&Bl[row][c4]     = l01;
            *(uint32_t*)&Bl[row][c4 + 2] = l23;
        }
        __syncthreads();

#pragma unroll
        for (int ks = 0; ks < 2; ks++) {
            const int kk = ks * 16;
            uint32_t bh[4][2], bl[4][2];
#pragma unroll
            for (int nt = 0; nt < 4; nt++) {
                const int n = wn * 32 + nt * 8 + gid;
                bh[nt][0] = *(const uint32_t*)&Bh[n][kk + 2 * tig];
                bh[nt][1] = *(const uint32_t*)&Bh[n][kk + 2 * tig + 8];
                bl[nt][0] = *(const uint32_t*)&Bl[n][kk + 2 * tig];
                bl[nt][1] = *(const uint32_t*)&Bl[n][kk + 2 * tig + 8];
            }
#pragma unroll
            for (int mt = 0; mt < 4; mt++) {
                const int m = wm * 64 + mt * 16;
                uint32_t ah[4], al[4];
                ah[0] = *(const uint32_t*)&Ah[m + gid][kk + 2 * tig];
                ah[1] = *(const uint32_t*)&Ah[m + gid + 8][kk + 2 * tig];
                ah[2] = *(const uint32_t*)&Ah[m + gid][kk + 2 * tig + 8];
                ah[3] = *(const uint32_t*)&Ah[m + gid + 8][kk + 2 * tig + 8];
                al[0] = *(const uint32_t*)&Al[m + gid][kk + 2 * tig];
                al[1] = *(const uint32_t*)&Al[m + gid + 8][kk + 2 * tig];
                al[2] = *(const uint32_t*)&Al[m + gid][kk + 2 * tig + 8];
                al[3] = *(const uint32_t*)&Al[m + gid + 8][kk + 2 * tig + 8];
#pragma unroll
                for (int nt = 0; nt < 4; nt++) {
                    mma_bf16(acc[mt][nt], ah, bh[nt]);   // hi*hi
                    mma_bf16(acc[mt][nt], ah, bl[nt]);   // hi*lo
                    mma_bf16(acc[mt][nt], al, bh[nt]);   // lo*hi
                }
            }
        }
    }

    // Epilogue: direct global stores from accumulators
#pragma unroll
    for (int mt = 0; mt < 4; mt++) {
#pragma unroll
        for (int nt = 0; nt < 4; nt++) {
            const int m = m0 + wm * 64 + mt * 16 + gid;
            const int n = n0 + wn * 32 + nt * 8 + 2 * tig;
            *(float2*)&C[(size_t)m * N + n] = make_float2(acc[mt][nt][0], acc[mt][nt][1]);
            *(float2*)&C[(size_t)(m + 8) * N + n] = make_float2(acc[mt][nt][2], acc[mt][nt][3]);
        }
    }
}

// Projections: z selects Q/K/V.  C = X @ W^T, M=4096, N=512, K=2048
__global__ __launch_bounds__(GTHREADS, 2)
void proj_tc_kernel(const float* __restrict__ q, const float* __restrict__ k,
                    const float* __restrict__ v, const float* __restrict__ Wq,
                    const float* __restrict__ Wk, const float* __restrict__ Wv) {
    const float* A;
    const float* W;
    float* C;
    if (blockIdx.z == 0)      { A = q; W = Wq; C = g_QH; }
    else if (blockIdx.z == 1) { A = k; W = Wk; C = g_KH; }
    else                      { A = v; W = Wv; C = g_VH; }
    tc_gemm_body(A, W, C, HID, PROJ);
}

// Output projection: out = AO @ Wo^T, M=4096, N=2048, K=512
__global__ __launch_bounds__(GTHREADS, 2)
void out_tc_kernel(const float* __restrict__ Wo, float* __restrict__ out) {
    tc_gemm_body(g_AO, Wo, out, PROJ, HID);
}

// ---------------------------------------------------------------------------
// Flash attention: one block = (128 query rows, one head, one batch).
// One thread = one query row. Online softmax in registers, 128-key smem tiles.
// ---------------------------------------------------------------------------
__global__ __launch_bounds__(128) void attn_kernel() {
    __shared__ float4 Ks[128][4];   // [key][d/4]
    __shared__ float4 Vs[128][4];

    const int t = threadIdx.x;                  // 0..127
    const int h = blockIdx.y;
    const int b = blockIdx.z;
    const int s = blockIdx.x * 128 + t;

    const float* qp = g_QH + ((size_t)(b * SEQ + s) * PROJ + h * HD);
    float4 q0 = ((const float4*)qp)[0];
    float4 q1 = ((const float4*)qp)[1];
    float4 q2 = ((const float4*)qp)[2];
    float4 q3 = ((const float4*)qp)[3];
    q0.x *= SCALE; q0.y *= SCALE; q0.z *= SCALE; q0.w *= SCALE;
    q1.x *= SCALE; q1.y *= SCALE; q1.z *= SCALE; q1.w *= SCALE;
    q2.x *= SCALE; q2.y *= SCALE; q2.z *= SCALE; q2.w *= SCALE;
    q3.x *= SCALE; q3.y *= SCALE; q3.z *= SCALE; q3.w *= SCALE;

    float m = -CUDART_INF_F;
    float l = 0.f;
    float o[16];
#pragma unroll
    for (int d = 0; d < 16; d++) o[d] = 0.f;

    const float* kbase = g_KH + ((size_t)b * SEQ * PROJ + h * HD);
    const float* vbase = g_VH + ((size_t)b * SEQ * PROJ + h * HD);

    for (int kt = 0; kt < SEQ; kt += 128) {
        __syncthreads();   // protect smem reuse from previous tile
        const float4* kp = (const float4*)(kbase + (size_t)(kt + t) * PROJ);
        const float4* vp = (const float4*)(vbase + (size_t)(kt + t) * PROJ);
        Ks[t][0] = kp[0]; Ks[t][1] = kp[1]; Ks[t][2] = kp[2]; Ks[t][3] = kp[3];
        Vs[t][0] = vp[0]; Vs[t][1] = vp[1]; Vs[t][2] = vp[2]; Vs[t][3] = vp[3];
        __syncthreads();

        for (int c = 0; c < 128; c += 16) {
            float sc[16];
#pragma unroll
            for (int j = 0; j < 16; j++) {
                float4 k0 = Ks[c + j][0];
                float4 k1 = Ks[c + j][1];
                float4 k2 = Ks[c + j][2];
                float4 k3 = Ks[c + j][3];
                sc[j] = q0.x * k0.x + q0.y * k0.y + q0.z * k0.z + q0.w * k0.w
                      + q1.x * k1.x + q1.y * k1.y + q1.z * k1.z + q1.w * k1.w
                      + q2.x * k2.x + q2.y * k2.y + q2.z * k2.z + q2.w * k2.w
                      + q3.x * k3.x + q3.y * k3.y + q3.z * k3.z + q3.w * k3.w;
            }
            float mc = sc[0];
#pragma unroll
            for (int j = 1; j < 16; j++) mc = fmaxf(mc, sc[j]);
            float mnew = fmaxf(m, mc);
            float alpha = __expf(m - mnew);
            l *= alpha;
#pragma unroll
            for (int d = 0; d < 16; d++) o[d] *= alpha;

#pragma unroll
            for (int j = 0; j < 16; j++) {
                float p = __expf(sc[j] - mnew);
                l += p;
                float4 v0 = Vs[c + j][0];
                float4 v1 = Vs[c + j][1];
                float4 v2 = Vs[c + j][2];
                float4 v3 = Vs[c + j][3];
                o[0]  += p * v0.x; o[1]  += p * v0.y; o[2]  += p * v0.z; o[3]  += p * v0.w;
                o[4]  += p * v1.x; o[5]  += p * v1.y; o[6]  += p * v1.z; o[7]  += p * v1.w;
                o[8]  += p * v2.x; o[9]  += p * v2.y; o[10] += p * v2.z; o[11] += p * v2.w;
                o[12] += p * v3.x; o[13] += p * v3.y; o[14] += p * v3.z; o[15] += p * v3.w;
            }
            m = mnew;
        }
    }

    const float inv = 1.f / l;
    float* op = g_AO + ((size_t)(b * SEQ + s) * PROJ + h * HD);
    ((float4*)op)[0] = make_float4(o[0]  * inv, o[1]  * inv, o[2]  * inv, o[3]  * inv);
    ((float4*)op)[1] = make_float4(o[4]  * inv, o[5]  * inv, o[6]  * inv, o[7]  * inv);
    ((float4*)op)[2] = make_float4(o[8]  * inv, o[9]  * inv, o[10] * inv, o[11] * inv);
    ((float4*)op)[3] = make_float4(o[12] * inv, o[13] * inv, o[14] * inv, o[15] * inv);
}

// ---------------------------------------------------------------------------
extern "C" void kernel_launch(void* const* d_in, const int* in_sizes, int n_in,
                              void* d_out, int out_size) {
    const float* q  = (const float*)d_in[0];
    const float* k  = (const float*)d_in[1];
    const float* v  = (const float*)d_in[2];
    const float* Wq = (const float*)d_in[3];
    const float* Wk = (const float*)d_in[4];
    const float* Wv = (const float*)d_in[5];
    const float* Wo = (const float*)d_in[6];
    float* out = (float*)d_out;

    // 1) Q/K/V projections (split-bf16 mma): M=4096, N=512, K=2048
    {
        dim3 grid(PROJ / GBN, MROWS / GBM, 3);
        proj_tc_kernel<<<grid, GTHREADS>>>(q, k, v, Wq, Wk, Wv);
    }
    // 2) Attention (flash-style, fp32)
    {
        dim3 grid(SEQ / 128, NHEAD, BSZ);
        attn_kernel<<<grid, 128>>>();
    }
    // 3) Output projection (split-bf16 mma): M=4096, N=2048, K=512
    {
        dim3 grid(HID / GBN, MROWS / GBM);
        out_tc_kernel<<<grid, GTHREADS>>>(Wo, out);
    }
}

// round 5
// speedup vs baseline: 1.6253x; 1.1672x over previous
#include <cuda_runtime.h>
#include <cuda_bf16.h>
#include <math_constants.h>
#include <cstdint>

// Problem constants
#define BSZ   2
#define SEQ   2048
#define HID   2048
#define NHEAD 32
#define HD    16
#define PROJ  512
#define MROWS (BSZ * SEQ)   // 4096
#define SCALE 0.125f        // (2048/8/4)^-0.5

typedef unsigned long long u64t;

// ---------------------------------------------------------------------------
// Persistent scratch (device globals — no allocation allowed)
// ---------------------------------------------------------------------------
__device__ __nv_bfloat16 g_IAh[(size_t)3 * MROWS * HID];   // q,k,v hi
__device__ __nv_bfloat16 g_IAl[(size_t)3 * MROWS * HID];   // q,k,v lo
__device__ __nv_bfloat16 g_WBh[(size_t)4 * PROJ * HID];    // Wq,Wk,Wv,Wo hi
__device__ __nv_bfloat16 g_WBl[(size_t)4 * PROJ * HID];    // Wq,Wk,Wv,Wo lo
__device__ float g_QH[MROWS * PROJ];
__device__ float g_KH[MROWS * PROJ];
__device__ float g_VH[MROWS * PROJ];
__device__ __nv_bfloat16 g_AOh[MROWS * PROJ];
__device__ __nv_bfloat16 g_AOl[MROWS * PROJ];

// ---------------------------------------------------------------------------
// Helpers
// ---------------------------------------------------------------------------
__device__ __forceinline__ void split2(float x, float y, uint32_t& hi, uint32_t& lo) {
    __nv_bfloat16 hx = __float2bfloat16_rn(x);
    __nv_bfloat16 hy = __float2bfloat16_rn(y);
    float rx = x - __bfloat162float(hx);
    float ry = y - __bfloat162float(hy);
    __nv_bfloat16 lx = __float2bfloat16_rn(rx);
    __nv_bfloat16 ly = __float2bfloat16_rn(ry);
    hi = (uint32_t)__bfloat16_as_ushort(hx) | ((uint32_t)__bfloat16_as_ushort(hy) << 16);
    lo = (uint32_t)__bfloat16_as_ushort(lx) | ((uint32_t)__bfloat16_as_ushort(ly) << 16);
}

__device__ __forceinline__ void mma_bf16(float* c, const uint32_t* a, const uint32_t* b) {
    asm volatile(
        "mma.sync.aligned.m16n8k16.row.col.f32.bf16.bf16.f32 "
        "{%0,%1,%2,%3}, {%4,%5,%6,%7}, {%8,%9}, {%0,%1,%2,%3};"
        : "+f"(c[0]), "+f"(c[1]), "+f"(c[2]), "+f"(c[3])
        : "r"(a[0]), "r"(a[1]), "r"(a[2]), "r"(a[3]), "r"(b[0]), "r"(b[1]));
}

__device__ __forceinline__ uint32_t smem_u32(const void* p) {
    uint32_t a;
    asm("{ .reg .u64 t; cvta.to.shared.u64 t, %1; cvt.u32.u64 %0, t; }" : "=r"(a) : "l"(p));
    return a;
}

__device__ __forceinline__ void cpasync16(uint32_t dst, const void* src) {
    asm volatile("cp.async.cg.shared.global [%0], [%1], 16;" :: "r"(dst), "l"(src) : "memory");
}
__device__ __forceinline__ void cpcommit() {
    asm volatile("cp.async.commit_group;" ::: "memory");
}
template <int N>
__device__ __forceinline__ void cpwait() {
    asm volatile("cp.async.wait_group %0;" :: "n"(N) : "memory");
}

// packed fp32 (f32x2) ops — Blackwell, PTX-only
__device__ __forceinline__ u64t pack2(float lo, float hi) {
    u64t r;
    asm("mov.b64 %0, {%1, %2};" : "=l"(r) : "f"(lo), "f"(hi));
    return r;
}
__device__ __forceinline__ void unpack2(u64t v, float& lo, float& hi) {
    asm("mov.b64 {%0, %1}, %2;" : "=f"(lo), "=f"(hi) : "l"(v));
}
__device__ __forceinline__ u64t fma2(u64t a, u64t b, u64t c) {
    u64t d;
    asm("fma.rn.f32x2 %0, %1, %2, %3;" : "=l"(d) : "l"(a), "l"(b), "l"(c));
    return d;
}
__device__ __forceinline__ u64t mul2(u64t a, u64t b) {
    u64t d;
    asm("mul.rn.f32x2 %0, %1, %2;" : "=l"(d) : "l"(a), "l"(b));
    return d;
}

// ---------------------------------------------------------------------------
// One-time split pass: float tensor -> bf16 hi/lo pair.
// which: 0..2 = q,k,v -> g_IA*; 3..5 = Wq,Wk,Wv; 6 = Wo -> g_WB*
// ---------------------------------------------------------------------------
__global__ __launch_bounds__(256) void split_kernel(const float4* __restrict__ src,
                                                    int which, int n4) {
    int i = blockIdx.x * 256 + threadIdx.x;
    if (i >= n4) return;
    __nv_bfloat16 *dh, *dl;
    size_t off;
    if (which < 3) { dh = g_IAh; dl = g_IAl; off = (size_t)which * MROWS * HID; }
    else           { dh = g_WBh; dl = g_WBl; off = (size_t)(which - 3) * PROJ * HID; }
    float4 v = src[i];
    uint32_t h01, l01, h23, l23;
    split2(v.x, v.y, h01, l01);
    split2(v.z, v.w, h23, l23);
    ((uint2*)(dh + off))[i] = make_uint2(h01, h23);
    ((uint2*)(dl + off))[i] = make_uint2(l01, l23);
}

// ===========================================================================
// Split-bf16 tensor-core GEMM with cp.async double-buffered pipeline.
// C[M,N] = A[M,K] @ W[N,K]^T ; A,W given as bf16 hi/lo arrays (K-major).
// CTA tile 128x128, K-chunk 32, 8 warps (warp tile 64x32), mma.m16n8k16.
// ===========================================================================
#define GBM 128
#define GBN 128
#define GBK 32
#define GTHREADS 256
#define ROWB 80                      // smem row: 64 B data + 16 B pad (conflict-free)
#define ROWE 40                      // row stride in bf16 elements
#define TILEB (128 * ROWB)           // 10240
#define OFF_AH 0
#define OFF_AL (1 * TILEB)
#define OFF_BH (2 * TILEB)
#define OFF_BL (3 * TILEB)
#define STAGE_B (4 * TILEB)          // 40960
#define GEMM_SMEM (2 * STAGE_B)      // 81920

__device__ __forceinline__ void tc_gemm_body(const __nv_bfloat16* __restrict__ Ahg,
                                             const __nv_bfloat16* __restrict__ Alg,
                                             const __nv_bfloat16* __restrict__ Bhg,
                                             const __nv_bfloat16* __restrict__ Blg,
                                             float* __restrict__ C,
                                             int K, int N) {
    extern __shared__ char smem[];
    const uint32_t sb = smem_u32(smem);

    const int tid = threadIdx.x;
    const int wid = tid >> 5;
    const int lane = tid & 31;
    const int wm = wid >> 2;          // 0..1
    const int wn = wid & 3;           // 0..3
    const int gid = lane >> 2;        // 0..7
    const int tig = lane & 3;         // 0..3

    const int m0 = blockIdx.y * GBM;
    const int n0 = blockIdx.x * GBN;
    const int nc = K / GBK;

    // copy-index decomposition: 512 16B chunks per tile buffer, 2 per thread
    const int crow0 = (tid + 0)   >> 2, cch0 = (tid + 0)   & 3;
    const int crow1 = (tid + 256) >> 2, cch1 = (tid + 256) & 3;

    float acc[4][4][4];
#pragma unroll
    for (int mt = 0; mt < 4; mt++)
#pragma unroll
        for (int nt = 0; nt < 4; nt++)
#pragma unroll
            for (int r = 0; r < 4; r++) acc[mt][nt][r] = 0.f;

    auto issue_stage = [&](int i) {
        const int s = i & 1;
        const int k0 = i * GBK;
        const uint32_t st = sb + s * STAGE_B;
        // two chunks per thread per buffer
        {
            const uint32_t d = (uint32_t)(crow0 * ROWB + cch0 * 16);
            const size_t ga = (size_t)(m0 + crow0) * K + k0 + cch0 * 8;
            const size_t gb = (size_t)(n0 + crow0) * K + k0 + cch0 * 8;
            cpasync16(st + OFF_AH + d, Ahg + ga);
            cpasync16(st + OFF_AL + d, Alg + ga);
            cpasync16(st + OFF_BH + d, Bhg + gb);
            cpasync16(st + OFF_BL + d, Blg + gb);
        }
        {
            const uint32_t d = (uint32_t)(crow1 * ROWB + cch1 * 16);
            const size_t ga = (size_t)(m0 + crow1) * K + k0 + cch1 * 8;
            const size_t gb = (size_t)(n0 + crow1) * K + k0 + cch1 * 8;
            cpasync16(st + OFF_AH + d, Ahg + ga);
            cpasync16(st + OFF_AL + d, Alg + ga);
            cpasync16(st + OFF_BH + d, Bhg + gb);
            cpasync16(st + OFF_BL + d, Blg + gb);
        }
    };

    issue_stage(0);
    cpcommit();

    for (int i = 0; i < nc; i++) {
        if (i + 1 < nc) {
            issue_stage(i + 1);
            cpcommit();
            cpwait<1>();
        } else {
            cpwait<0>();
        }
        __syncthreads();

        const int s = i & 1;
        const __nv_bfloat16* Ahs = (const __nv_bfloat16*)(smem + s * STAGE_B + OFF_AH);
        const __nv_bfloat16* Als = (const __nv_bfloat16*)(smem + s * STAGE_B + OFF_AL);
        const __nv_bfloat16* Bhs = (const __nv_bfloat16*)(smem + s * STAGE_B + OFF_BH);
        const __nv_bfloat16* Bls = (const __nv_bfloat16*)(smem + s * STAGE_B + OFF_BL);

#pragma unroll
        for (int ks = 0; ks < 2; ks++) {
            const int kk = ks * 16;
            uint32_t bh[4][2], bl[4][2];
#pragma unroll
            for (int nt = 0; nt < 4; nt++) {
                const int n = wn * 32 + nt * 8 + gid;
                bh[nt][0] = *(const uint32_t*)&Bhs[n * ROWE + kk + 2 * tig];
                bh[nt][1] = *(const uint32_t*)&Bhs[n * ROWE + kk + 2 * tig + 8];
                bl[nt][0] = *(const uint32_t*)&Bls[n * ROWE + kk + 2 * tig];
                bl[nt][1] = *(const uint32_t*)&Bls[n * ROWE + kk + 2 * tig + 8];
            }
#pragma unroll
            for (int mt = 0; mt < 4; mt++) {
                const int m = wm * 64 + mt * 16;
                uint32_t ah[4], al[4];
                ah[0] = *(const uint32_t*)&Ahs[(m + gid) * ROWE + kk + 2 * tig];
                ah[1] = *(const uint32_t*)&Ahs[(m + gid + 8) * ROWE + kk + 2 * tig];
                ah[2] = *(const uint32_t*)&Ahs[(m + gid) * ROWE + kk + 2 * tig + 8];
                ah[3] = *(const uint32_t*)&Ahs[(m + gid + 8) * ROWE + kk + 2 * tig + 8];
                al[0] = *(const uint32_t*)&Als[(m + gid) * ROWE + kk + 2 * tig];
                al[1] = *(const uint32_t*)&Als[(m + gid + 8) * ROWE + kk + 2 * tig];
                al[2] = *(const uint32_t*)&Als[(m + gid) * ROWE + kk + 2 * tig + 8];
                al[3] = *(const uint32_t*)&Als[(m + gid + 8) * ROWE + kk + 2 * tig + 8];
#pragma unroll
                for (int nt = 0; nt < 4; nt++) {
                    mma_bf16(acc[mt][nt], ah, bh[nt]);   // hi*hi
                    mma_bf16(acc[mt][nt], ah, bl[nt]);   // hi*lo
                    mma_bf16(acc[mt][nt], al, bh[nt]);   // lo*hi
                }
            }
        }
        __syncthreads();
    }

    // Epilogue: direct global stores from accumulators
#pragma unroll
    for (int mt = 0; mt < 4; mt++) {
#pragma unroll
        for (int nt = 0; nt < 4; nt++) {
            const int m = m0 + wm * 64 + mt * 16 + gid;
            const int n = n0 + wn * 32 + nt * 8 + 2 * tig;
            *(float2*)&C[(size_t)m * N + n] = make_float2(acc[mt][nt][0], acc[mt][nt][1]);
            *(float2*)&C[(size_t)(m + 8) * N + n] = make_float2(acc[mt][nt][2], acc[mt][nt][3]);
        }
    }
}

// Projections: z selects Q/K/V.  C = X @ W^T, M=4096, N=512, K=2048
__global__ __launch_bounds__(GTHREADS, 2)
void proj_tc_kernel() {
    const size_t za = (size_t)blockIdx.z * MROWS * HID;
    const size_t zw = (size_t)blockIdx.z * PROJ * HID;
    float* C = (blockIdx.z == 0) ? g_QH : (blockIdx.z == 1) ? g_KH : g_VH;
    tc_gemm_body(g_IAh + za, g_IAl + za, g_WBh + zw, g_WBl + zw, C, HID, PROJ);
}

// Output projection: out = AO @ Wo^T, M=4096, N=2048, K=512
__global__ __launch_bounds__(GTHREADS, 2)
void out_tc_kernel(float* __restrict__ out) {
    const size_t zw = (size_t)3 * PROJ * HID;
    tc_gemm_body(g_AOh, g_AOl, g_WBh + zw, g_WBl + zw, out, PROJ, HID);
}

// ---------------------------------------------------------------------------
// Flash attention with packed f32x2 math.
// One block = (128 query rows, one head, one batch); one thread = one query.
// Q pre-scaled by SCALE*log2(e); softmax via exp2f. Writes bf16 hi/lo AO.
// ---------------------------------------------------------------------------
__global__ __launch_bounds__(128) void attn_kernel() {
    __shared__ float4 Ks[128][4];   // [key][d/4]
    __shared__ float4 Vs[128][4];

    const int t = threadIdx.x;
    const int h = blockIdx.y;
    const int b = blockIdx.z;
    const int s = blockIdx.x * 128 + t;

    const float* qp = g_QH + ((size_t)(b * SEQ + s) * PROJ + h * HD);
    const float SC = SCALE * 1.4426950408889634f;    // fold log2(e) into scale
    const u64t sc2 = pack2(SC, SC);
    u64t q2[8];
    const u64t* qp2 = (const u64t*)qp;
#pragma unroll
    for (int d = 0; d < 8; d++) q2[d] = mul2(qp2[d], sc2);

    float m = -CUDART_INF_F;
    float l = 0.f;
    u64t o2[8];
#pragma unroll
    for (int d = 0; d < 8; d++) o2[d] = pack2(0.f, 0.f);

    const float* kbase = g_KH + ((size_t)b * SEQ * PROJ + h * HD);
    const float* vbase = g_VH + ((size_t)b * SEQ * PROJ + h * HD);

    for (int kt = 0; kt < SEQ; kt += 128) {
        __syncthreads();
        const float4* kp = (const float4*)(kbase + (size_t)(kt + t) * PROJ);
        const float4* vp = (const float4*)(vbase + (size_t)(kt + t) * PROJ);
        Ks[t][0] = kp[0]; Ks[t][1] = kp[1]; Ks[t][2] = kp[2]; Ks[t][3] = kp[3];
        Vs[t][0] = vp[0]; Vs[t][1] = vp[1]; Vs[t][2] = vp[2]; Vs[t][3] = vp[3];
        __syncthreads();

        for (int c = 0; c < 128; c += 16) {
            float sc[16];
#pragma unroll
            for (int j = 0; j < 16; j++) {
                const u64t* kr = (const u64t*)&Ks[c + j][0];
                u64t acc = mul2(q2[0], kr[0]);
#pragma unroll
                for (int d = 1; d < 8; d++) acc = fma2(q2[d], kr[d], acc);
                float lo, hi;
                unpack2(acc, lo, hi);
                sc[j] = lo + hi;
            }
            float mc = sc[0];
#pragma unroll
            for (int j = 1; j < 16; j++) mc = fmaxf(mc, sc[j]);
            float mnew = fmaxf(m, mc);
            float alpha = exp2f(m - mnew);
            l *= alpha;
            const u64t a2 = pack2(alpha, alpha);
#pragma unroll
            for (int d = 0; d < 8; d++) o2[d] = mul2(o2[d], a2);

#pragma unroll
            for (int j = 0; j < 16; j++) {
                float p = exp2f(sc[j] - mnew);
                l += p;
                const u64t p2 = pack2(p, p);
                const u64t* vr = (const u64t*)&Vs[c + j][0];
#pragma unroll
                for (int d = 0; d < 8; d++) o2[d] = fma2(p2, vr[d], o2[d]);
            }
            m = mnew;
        }
    }

    const float inv = 1.f / l;
    uint32_t hh[8], ll[8];
#pragma unroll
    for (int d = 0; d < 8; d++) {
        float lo, hi;
        unpack2(o2[d], lo, hi);
        split2(lo * inv, hi * inv, hh[d], ll[d]);
    }
    const size_t off = (size_t)(b * SEQ + s) * PROJ + h * HD;
    ((uint4*)(g_AOh + off))[0] = make_uint4(hh[0], hh[1], hh[2], hh[3]);
    ((uint4*)(g_AOh + off))[1] = make_uint4(hh[4], hh[5], hh[6], hh[7]);
    ((uint4*)(g_AOl + off))[0] = make_uint4(ll[0], ll[1], ll[2], ll[3]);
    ((uint4*)(g_AOl + off))[1] = make_uint4(ll[4], ll[5], ll[6], ll[7]);
}

// ---------------------------------------------------------------------------
extern "C" void kernel_launch(void* const* d_in, const int* in_sizes, int n_in,
                              void* d_out, int out_size) {
    const float* q  = (const float*)d_in[0];
    const float* k  = (const float*)d_in[1];
    const float* v  = (const float*)d_in[2];
    const float* Wq = (const float*)d_in[3];
    const float* Wk = (const float*)d_in[4];
    const float* Wv = (const float*)d_in[5];
    const float* Wo = (const float*)d_in[6];
    float* out = (float*)d_out;

    cudaFuncSetAttribute(proj_tc_kernel,
                         cudaFuncAttributeMaxDynamicSharedMemorySize, GEMM_SMEM);
    cudaFuncSetAttribute(out_tc_kernel,
                         cudaFuncAttributeMaxDynamicSharedMemorySize, GEMM_SMEM);

    // 0) split all inputs/weights into bf16 hi/lo
    const int n4_in = MROWS * HID / 4;     // 2,097,152
    const int n4_w  = PROJ * HID / 4;      // 262,144
    split_kernel<<<(n4_in + 255) / 256, 256>>>((const float4*)q,  0, n4_in);
    split_kernel<<<(n4_in + 255) / 256, 256>>>((const float4*)k,  1, n4_in);
    split_kernel<<<(n4_in + 255) / 256, 256>>>((const float4*)v,  2, n4_in);
    split_kernel<<<(n4_w  + 255) / 256, 256>>>((const float4*)Wq, 3, n4_w);
    split_kernel<<<(n4_w  + 255) / 256, 256>>>((const float4*)Wk, 4, n4_w);
    split_kernel<<<(n4_w  + 255) / 256, 256>>>((const float4*)Wv, 5, n4_w);
    split_kernel<<<(n4_w  + 255) / 256, 256>>>((const float4*)Wo, 6, n4_w);

    // 1) Q/K/V projections: M=4096, N=512, K=2048
    {
        dim3 grid(PROJ / GBN, MROWS / GBM, 3);
        proj_tc_kernel<<<grid, GTHREADS, GEMM_SMEM>>>();
    }
    // 2) Attention (flash-style, packed f32x2)
    {
        dim3 grid(SEQ / 128, NHEAD, BSZ);
        attn_kernel<<<grid, 128>>>();
    }
    // 3) Output projection: M=4096, N=2048, K=512
    {
        dim3 grid(HID / GBN, MROWS / GBM);
        out_tc_kernel<<<grid, GTHREADS, GEMM_SMEM>>>(out);
    }
}

// round 6
// speedup vs baseline: 2.4681x; 1.5185x over previous
#include <cuda_runtime.h>
#include <cuda_bf16.h>
#include <math_constants.h>
#include <cstdint>

// Problem constants
#define BSZ   2
#define SEQ   2048
#define HID   2048
#define NHEAD 32
#define HD    16
#define PROJ  512
#define MROWS (BSZ * SEQ)   // 4096
#define SCALE 0.125f        // (2048/8/4)^-0.5
#define QPRE  (0.125f * 1.4426950408889634f)   // SCALE * log2(e)

// ---------------------------------------------------------------------------
// Persistent scratch (device globals — no allocation allowed)
// ---------------------------------------------------------------------------
__device__ __nv_bfloat16 g_IAh[(size_t)3 * MROWS * HID];   // q,k,v input hi
__device__ __nv_bfloat16 g_IAl[(size_t)3 * MROWS * HID];   // q,k,v input lo
__device__ __nv_bfloat16 g_WBh[(size_t)4 * PROJ * HID];    // Wq,Wk,Wv,Wo hi
__device__ __nv_bfloat16 g_WBl[(size_t)4 * PROJ * HID];    // Wq,Wk,Wv,Wo lo
__device__ __nv_bfloat16 g_Qh[MROWS * PROJ];               // projected, pre-scaled
__device__ __nv_bfloat16 g_Ql[MROWS * PROJ];
__device__ __nv_bfloat16 g_Kh[MROWS * PROJ];
__device__ __nv_bfloat16 g_Kl[MROWS * PROJ];
__device__ __nv_bfloat16 g_Vh[MROWS * PROJ];
__device__ __nv_bfloat16 g_Vl[MROWS * PROJ];
__device__ __nv_bfloat16 g_AOh[MROWS * PROJ];
__device__ __nv_bfloat16 g_AOl[MROWS * PROJ];

// ---------------------------------------------------------------------------
// Helpers
// ---------------------------------------------------------------------------
__device__ __forceinline__ void split2(float x, float y, uint32_t& hi, uint32_t& lo) {
    __nv_bfloat16 hx = __float2bfloat16_rn(x);
    __nv_bfloat16 hy = __float2bfloat16_rn(y);
    float rx = x - __bfloat162float(hx);
    float ry = y - __bfloat162float(hy);
    __nv_bfloat16 lx = __float2bfloat16_rn(rx);
    __nv_bfloat16 ly = __float2bfloat16_rn(ry);
    hi = (uint32_t)__bfloat16_as_ushort(hx) | ((uint32_t)__bfloat16_as_ushort(hy) << 16);
    lo = (uint32_t)__bfloat16_as_ushort(lx) | ((uint32_t)__bfloat16_as_ushort(ly) << 16);
}

__device__ __forceinline__ void mma_bf16(float* c, const uint32_t* a, const uint32_t* b) {
    asm volatile(
        "mma.sync.aligned.m16n8k16.row.col.f32.bf16.bf16.f32 "
        "{%0,%1,%2,%3}, {%4,%5,%6,%7}, {%8,%9}, {%0,%1,%2,%3};"
        : "+f"(c[0]), "+f"(c[1]), "+f"(c[2]), "+f"(c[3])
        : "r"(a[0]), "r"(a[1]), "r"(a[2]), "r"(a[3]), "r"(b[0]), "r"(b[1]));
}

__device__ __forceinline__ uint32_t smem_u32(const void* p) {
    uint32_t a;
    asm("{ .reg .u64 t; cvta.to.shared.u64 t, %1; cvt.u32.u64 %0, t; }" : "=r"(a) : "l"(p));
    return a;
}

__device__ __forceinline__ void cpasync16(uint32_t dst, const void* src) {
    asm volatile("cp.async.cg.shared.global [%0], [%1], 16;" :: "r"(dst), "l"(src) : "memory");
}
__device__ __forceinline__ void cpcommit() {
    asm volatile("cp.async.commit_group;" ::: "memory");
}
template <int N>
__device__ __forceinline__ void cpwait() {
    asm volatile("cp.async.wait_group %0;" :: "n"(N) : "memory");
}

// ---------------------------------------------------------------------------
// One-time split pass: float tensor -> bf16 hi/lo pair.
// which: 0..2 = q,k,v -> g_IA*; 3..6 = Wq,Wk,Wv,Wo -> g_WB*
// ---------------------------------------------------------------------------
__global__ __launch_bounds__(256) void split_kernel(const float4* __restrict__ src,
                                                    int which, int n4) {
    int i = blockIdx.x * 256 + threadIdx.x;
    if (i >= n4) return;
    __nv_bfloat16 *dh, *dl;
    size_t off;
    if (which < 3) { dh = g_IAh; dl = g_IAl; off = (size_t)which * MROWS * HID; }
    else           { dh = g_WBh; dl = g_WBl; off = (size_t)(which - 3) * PROJ * HID; }
    float4 v = src[i];
    uint32_t h01, l01, h23, l23;
    split2(v.x, v.y, h01, l01);
    split2(v.z, v.w, h23, l23);
    ((uint2*)(dh + off))[i] = make_uint2(h01, h23);
    ((uint2*)(dl + off))[i] = make_uint2(l01, l23);
}

// ===========================================================================
// Split-bf16 tensor-core GEMM with cp.async double-buffered pipeline.
// C[M,N] = A[M,K] @ W[N,K]^T. Epilogue: either fp32 store (Cf) or
// prescaled bf16 hi/lo split store (Chi/Clo).
// ===========================================================================
#define GBM 128
#define GBN 128
#define GBK 32
#define GTHREADS 256
#define ROWB 80
#define ROWE 40
#define TILEB (128 * ROWB)
#define OFF_AH 0
#define OFF_AL (1 * TILEB)
#define OFF_BH (2 * TILEB)
#define OFF_BL (3 * TILEB)
#define STAGE_B (4 * TILEB)
#define GEMM_SMEM (2 * STAGE_B)

__device__ __forceinline__ void tc_gemm_body(const __nv_bfloat16* __restrict__ Ahg,
                                             const __nv_bfloat16* __restrict__ Alg,
                                             const __nv_bfloat16* __restrict__ Bhg,
                                             const __nv_bfloat16* __restrict__ Blg,
                                             float* __restrict__ Cf,
                                             __nv_bfloat16* __restrict__ Chi,
                                             __nv_bfloat16* __restrict__ Clo,
                                             float pre,
                                             int K, int N) {
    extern __shared__ char smem[];
    const uint32_t sb = smem_u32(smem);

    const int tid = threadIdx.x;
    const int wid = tid >> 5;
    const int lane = tid & 31;
    const int wm = wid >> 2;
    const int wn = wid & 3;
    const int gid = lane >> 2;
    const int tig = lane & 3;

    const int m0 = blockIdx.y * GBM;
    const int n0 = blockIdx.x * GBN;
    const int nc = K / GBK;

    const int crow0 = (tid + 0)   >> 2, cch0 = (tid + 0)   & 3;
    const int crow1 = (tid + 256) >> 2, cch1 = (tid + 256) & 3;

    float acc[4][4][4];
#pragma unroll
    for (int mt = 0; mt < 4; mt++)
#pragma unroll
        for (int nt = 0; nt < 4; nt++)
#pragma unroll
            for (int r = 0; r < 4; r++) acc[mt][nt][r] = 0.f;

    auto issue_stage = [&](int i) {
        const int s = i & 1;
        const int k0 = i * GBK;
        const uint32_t st = sb + s * STAGE_B;
        {
            const uint32_t d = (uint32_t)(crow0 * ROWB + cch0 * 16);
            const size_t ga = (size_t)(m0 + crow0) * K + k0 + cch0 * 8;
            const size_t gb = (size_t)(n0 + crow0) * K + k0 + cch0 * 8;
            cpasync16(st + OFF_AH + d, Ahg + ga);
            cpasync16(st + OFF_AL + d, Alg + ga);
            cpasync16(st + OFF_BH + d, Bhg + gb);
            cpasync16(st + OFF_BL + d, Blg + gb);
        }
        {
            const uint32_t d = (uint32_t)(crow1 * ROWB + cch1 * 16);
            const size_t ga = (size_t)(m0 + crow1) * K + k0 + cch1 * 8;
            const size_t gb = (size_t)(n0 + crow1) * K + k0 + cch1 * 8;
            cpasync16(st + OFF_AH + d, Ahg + ga);
            cpasync16(st + OFF_AL + d, Alg + ga);
            cpasync16(st + OFF_BH + d, Bhg + gb);
            cpasync16(st + OFF_BL + d, Blg + gb);
        }
    };

    issue_stage(0);
    cpcommit();

    for (int i = 0; i < nc; i++) {
        if (i + 1 < nc) {
            issue_stage(i + 1);
            cpcommit();
            cpwait<1>();
        } else {
            cpwait<0>();
        }
        __syncthreads();

        const int s = i & 1;
        const __nv_bfloat16* Ahs = (const __nv_bfloat16*)(smem + s * STAGE_B + OFF_AH);
        const __nv_bfloat16* Als = (const __nv_bfloat16*)(smem + s * STAGE_B + OFF_AL);
        const __nv_bfloat16* Bhs = (const __nv_bfloat16*)(smem + s * STAGE_B + OFF_BH);
        const __nv_bfloat16* Bls = (const __nv_bfloat16*)(smem + s * STAGE_B + OFF_BL);

#pragma unroll
        for (int ks = 0; ks < 2; ks++) {
            const int kk = ks * 16;
            uint32_t bh[4][2], bl[4][2];
#pragma unroll
            for (int nt = 0; nt < 4; nt++) {
                const int n = wn * 32 + nt * 8 + gid;
                bh[nt][0] = *(const uint32_t*)&Bhs[n * ROWE + kk + 2 * tig];
                bh[nt][1] = *(const uint32_t*)&Bhs[n * ROWE + kk + 2 * tig + 8];
                bl[nt][0] = *(const uint32_t*)&Bls[n * ROWE + kk + 2 * tig];
                bl[nt][1] = *(const uint32_t*)&Bls[n * ROWE + kk + 2 * tig + 8];
            }
#pragma unroll
            for (int mt = 0; mt < 4; mt++) {
                const int m = wm * 64 + mt * 16;
                uint32_t ah[4], al[4];
                ah[0] = *(const uint32_t*)&Ahs[(m + gid) * ROWE + kk + 2 * tig];
                ah[1] = *(const uint32_t*)&Ahs[(m + gid + 8) * ROWE + kk + 2 * tig];
                ah[2] = *(const uint32_t*)&Ahs[(m + gid) * ROWE + kk + 2 * tig + 8];
                ah[3] = *(const uint32_t*)&Ahs[(m + gid + 8) * ROWE + kk + 2 * tig + 8];
                al[0] = *(const uint32_t*)&Als[(m + gid) * ROWE + kk + 2 * tig];
                al[1] = *(const uint32_t*)&Als[(m + gid + 8) * ROWE + kk + 2 * tig];
                al[2] = *(const uint32_t*)&Als[(m + gid) * ROWE + kk + 2 * tig + 8];
                al[3] = *(const uint32_t*)&Als[(m + gid + 8) * ROWE + kk + 2 * tig + 8];
#pragma unroll
                for (int nt = 0; nt < 4; nt++) {
                    mma_bf16(acc[mt][nt], ah, bh[nt]);
                    mma_bf16(acc[mt][nt], ah, bl[nt]);
                    mma_bf16(acc[mt][nt], al, bh[nt]);
                }
            }
        }
        __syncthreads();
    }

#pragma unroll
    for (int mt = 0; mt < 4; mt++) {
#pragma unroll
        for (int nt = 0; nt < 4; nt++) {
            const int m = m0 + wm * 64 + mt * 16 + gid;
            const int n = n0 + wn * 32 + nt * 8 + 2 * tig;
            if (Cf) {
                *(float2*)&Cf[(size_t)m * N + n] = make_float2(acc[mt][nt][0], acc[mt][nt][1]);
                *(float2*)&Cf[(size_t)(m + 8) * N + n] = make_float2(acc[mt][nt][2], acc[mt][nt][3]);
            } else {
                uint32_t hi, lo;
                split2(acc[mt][nt][0] * pre, acc[mt][nt][1] * pre, hi, lo);
                *(uint32_t*)&Chi[(size_t)m * N + n] = hi;
                *(uint32_t*)&Clo[(size_t)m * N + n] = lo;
                split2(acc[mt][nt][2] * pre, acc[mt][nt][3] * pre, hi, lo);
                *(uint32_t*)&Chi[(size_t)(m + 8) * N + n] = hi;
                *(uint32_t*)&Clo[(size_t)(m + 8) * N + n] = lo;
            }
        }
    }
}

// Projections: z selects Q/K/V; writes split bf16 (Q pre-scaled).
__global__ __launch_bounds__(GTHREADS, 2)
void proj_tc_kernel() {
    const size_t za = (size_t)blockIdx.z * MROWS * HID;
    const size_t zw = (size_t)blockIdx.z * PROJ * HID;
    __nv_bfloat16 *Chi, *Clo;
    float pre = 1.f;
    if (blockIdx.z == 0)      { Chi = g_Qh; Clo = g_Ql; pre = QPRE; }
    else if (blockIdx.z == 1) { Chi = g_Kh; Clo = g_Kl; }
    else                      { Chi = g_Vh; Clo = g_Vl; }
    tc_gemm_body(g_IAh + za, g_IAl + za, g_WBh + zw, g_WBl + zw,
                 nullptr, Chi, Clo, pre, HID, PROJ);
}

// Output projection: out = AO @ Wo^T (fp32 out)
__global__ __launch_bounds__(GTHREADS, 2)
void out_tc_kernel(float* __restrict__ out) {
    const size_t zw = (size_t)3 * PROJ * HID;
    tc_gemm_body(g_AOh, g_AOl, g_WBh + zw, g_WBl + zw,
                 out, nullptr, nullptr, 1.f, PROJ, HID);
}

// ===========================================================================
// Tensor-core flash attention.
// Block = 256 threads (8 warps) x 128 query rows; warp owns 16 rows.
// Key blocks of 128. Scores & PV via mma.m16n8k16, 3-term bf16 split.
// Q pre-scaled by SCALE*log2(e) -> softmax in exp2 domain.
// ===========================================================================
__global__ __launch_bounds__(256, 2) void attn_mma_kernel() {
    __shared__ __align__(16) __nv_bfloat16 Kh[128][16];
    __shared__ __align__(16) __nv_bfloat16 Kl[128][16];
    __shared__ __align__(16) __nv_bfloat16 Vth[16][136];   // transposed, padded
    __shared__ __align__(16) __nv_bfloat16 Vtl[16][136];

    const int tid = threadIdx.x;
    const int wid = tid >> 5;
    const int lane = tid & 31;
    const int gid = lane >> 2;
    const int tig = lane & 3;
    const int h = blockIdx.y;
    const int b = blockIdx.z;
    const int q0 = blockIdx.x * 128;

    // Q fragments (persistent, hi/lo)
    const size_t qrow = (size_t)(b * SEQ + q0 + wid * 16);
    uint32_t qh[4], ql[4];
    {
        const __nv_bfloat16* Q0 = g_Qh + (qrow + gid) * PROJ + h * HD;
        const __nv_bfloat16* Q8 = g_Qh + (qrow + gid + 8) * PROJ + h * HD;
        qh[0] = *(const uint32_t*)(Q0 + 2 * tig);
        qh[1] = *(const uint32_t*)(Q8 + 2 * tig);
        qh[2] = *(const uint32_t*)(Q0 + 2 * tig + 8);
        qh[3] = *(const uint32_t*)(Q8 + 2 * tig + 8);
        const __nv_bfloat16* q0l = g_Ql + (qrow + gid) * PROJ + h * HD;
        const __nv_bfloat16* q8l = g_Ql + (qrow + gid + 8) * PROJ + h * HD;
        ql[0] = *(const uint32_t*)(q0l + 2 * tig);
        ql[1] = *(const uint32_t*)(q8l + 2 * tig);
        ql[2] = *(const uint32_t*)(q0l + 2 * tig + 8);
        ql[3] = *(const uint32_t*)(q8l + 2 * tig + 8);
    }

    float m0v = -CUDART_INF_F, m1v = -CUDART_INF_F;
    float l0 = 0.f, l1 = 0.f;
    float o[2][4];
#pragma unroll
    for (int a = 0; a < 2; a++)
#pragma unroll
        for (int r = 0; r < 4; r++) o[a][r] = 0.f;

    for (int kt = 0; kt < SEQ; kt += 128) {
        __syncthreads();
        // stage K (all 256 threads): 128 rows x 32B per array
        {
            const int srow = tid >> 1, shalf = tid & 1;
            const size_t src = ((size_t)(b * SEQ + kt) + srow) * PROJ + h * HD + shalf * 8;
            *(uint4*)&Kh[srow][shalf * 8] = *(const uint4*)(g_Kh + src);
            *(uint4*)&Kl[srow][shalf * 8] = *(const uint4*)(g_Kl + src);
        }
        // stage V transposed: threads 0-127 hi, 128-255 lo
        {
            const int key = tid & 127;
            const __nv_bfloat16* vsrc = (tid < 128 ? g_Vh : g_Vl)
                + ((size_t)(b * SEQ + kt) + key) * PROJ + h * HD;
            __nv_bfloat16* vdst = (tid < 128) ? &Vth[0][0] : &Vtl[0][0];
            __nv_bfloat16 tmp[16];
            *(uint4*)tmp = *(const uint4*)vsrc;
            *(uint4*)(tmp + 8) = *(const uint4*)(vsrc + 8);
#pragma unroll
            for (int d = 0; d < 16; d++) vdst[d * 136 + key] = tmp[d];
        }
        __syncthreads();

        // scores: 16 n-tiles of 8 keys
        float sc[16][4];
#pragma unroll
        for (int nt = 0; nt < 16; nt++) {
            uint32_t bh[2], bl[2];
            bh[0] = *(const uint32_t*)&Kh[nt * 8 + gid][2 * tig];
            bh[1] = *(const uint32_t*)&Kh[nt * 8 + gid][2 * tig + 8];
            bl[0] = *(const uint32_t*)&Kl[nt * 8 + gid][2 * tig];
            bl[1] = *(const uint32_t*)&Kl[nt * 8 + gid][2 * tig + 8];
            sc[nt][0] = sc[nt][1] = sc[nt][2] = sc[nt][3] = 0.f;
            mma_bf16(sc[nt], qh, bh);
            mma_bf16(sc[nt], qh, bl);
            mma_bf16(sc[nt], ql, bh);
        }

        // row max (rows r0 = gid, r1 = gid+8)
        float mx0 = sc[0][0], mx1 = sc[0][2];
#pragma unroll
        for (int nt = 0; nt < 16; nt++) {
            mx0 = fmaxf(mx0, fmaxf(sc[nt][0], sc[nt][1]));
            mx1 = fmaxf(mx1, fmaxf(sc[nt][2], sc[nt][3]));
        }
        mx0 = fmaxf(mx0, __shfl_xor_sync(0xffffffffu, mx0, 1));
        mx0 = fmaxf(mx0, __shfl_xor_sync(0xffffffffu, mx0, 2));
        mx1 = fmaxf(mx1, __shfl_xor_sync(0xffffffffu, mx1, 1));
        mx1 = fmaxf(mx1, __shfl_xor_sync(0xffffffffu, mx1, 2));

        const float mn0 = fmaxf(m0v, mx0);
        const float mn1 = fmaxf(m1v, mx1);
        const float al0 = exp2f(m0v - mn0);
        const float al1 = exp2f(m1v - mn1);
        m0v = mn0; m1v = mn1;
        l0 *= al0; l1 *= al1;
#pragma unroll
        for (int a = 0; a < 2; a++) {
            o[a][0] *= al0; o[a][1] *= al0;
            o[a][2] *= al1; o[a][3] *= al1;
        }

        // P (exp2) + PV mma, key chunks of 16
        float s0 = 0.f, s1 = 0.f;
#pragma unroll
        for (int kc = 0; kc < 8; kc++) {
            float p[8];
            p[0] = exp2f(sc[2 * kc][0] - m0v);
            p[1] = exp2f(sc[2 * kc][1] - m0v);
            p[2] = exp2f(sc[2 * kc][2] - m1v);
            p[3] = exp2f(sc[2 * kc][3] - m1v);
            p[4] = exp2f(sc[2 * kc + 1][0] - m0v);
            p[5] = exp2f(sc[2 * kc + 1][1] - m0v);
            p[6] = exp2f(sc[2 * kc + 1][2] - m1v);
            p[7] = exp2f(sc[2 * kc + 1][3] - m1v);
            s0 += p[0] + p[1] + p[4] + p[5];
            s1 += p[2] + p[3] + p[6] + p[7];

            uint32_t ah[4], al[4];
#pragma unroll
            for (int j = 0; j < 4; j++) {
                __nv_bfloat162 hv = __floats2bfloat162_rn(p[2 * j], p[2 * j + 1]);
                ah[j] = *(uint32_t*)&hv;
                float rlo = p[2 * j] - __bfloat162float(hv.x);
                float rhi = p[2 * j + 1] - __bfloat162float(hv.y);
                __nv_bfloat162 lv = __floats2bfloat162_rn(rlo, rhi);
                al[j] = *(uint32_t*)&lv;
            }
#pragma unroll
            for (int nt2 = 0; nt2 < 2; nt2++) {
                uint32_t bvh[2], bvl[2];
                bvh[0] = *(const uint32_t*)&Vth[nt2 * 8 + gid][kc * 16 + 2 * tig];
                bvh[1] = *(const uint32_t*)&Vth[nt2 * 8 + gid][kc * 16 + 8 + 2 * tig];
                bvl[0] = *(const uint32_t*)&Vtl[nt2 * 8 + gid][kc * 16 + 2 * tig];
                bvl[1] = *(const uint32_t*)&Vtl[nt2 * 8 + gid][kc * 16 + 8 + 2 * tig];
                mma_bf16(o[nt2], ah, bvh);
                mma_bf16(o[nt2], ah, bvl);
                mma_bf16(o[nt2], al, bvh);
            }
        }
        s0 += __shfl_xor_sync(0xffffffffu, s0, 1);
        s0 += __shfl_xor_sync(0xffffffffu, s0, 2);
        s1 += __shfl_xor_sync(0xffffffffu, s1, 1);
        s1 += __shfl_xor_sync(0xffffffffu, s1, 2);
        l0 += s0; l1 += s1;
    }

    // epilogue: O/l -> AO hi/lo
    const float i0 = 1.f / l0;
    const float i1 = 1.f / l1;
    const size_t rA = (qrow + gid) * PROJ + h * HD;
    const size_t rB = (qrow + gid + 8) * PROJ + h * HD;
#pragma unroll
    for (int nt2 = 0; nt2 < 2; nt2++) {
        uint32_t hi, lo;
        split2(o[nt2][0] * i0, o[nt2][1] * i0, hi, lo);
        *(uint32_t*)&g_AOh[rA + nt2 * 8 + 2 * tig] = hi;
        *(uint32_t*)&g_AOl[rA + nt2 * 8 + 2 * tig] = lo;
        split2(o[nt2][2] * i1, o[nt2][3] * i1, hi, lo);
        *(uint32_t*)&g_AOh[rB + nt2 * 8 + 2 * tig] = hi;
        *(uint32_t*)&g_AOl[rB + nt2 * 8 + 2 * tig] = lo;
    }
}

// ---------------------------------------------------------------------------
extern "C" void kernel_launch(void* const* d_in, const int* in_sizes, int n_in,
                              void* d_out, int out_size) {
    const float* q  = (const float*)d_in[0];
    const float* k  = (const float*)d_in[1];
    const float* v  = (const float*)d_in[2];
    const float* Wq = (const float*)d_in[3];
    const float* Wk = (const float*)d_in[4];
    const float* Wv = (const float*)d_in[5];
    const float* Wo = (const float*)d_in[6];
    float* out = (float*)d_out;

    cudaFuncSetAttribute(proj_tc_kernel,
                         cudaFuncAttributeMaxDynamicSharedMemorySize, GEMM_SMEM);
    cudaFuncSetAttribute(out_tc_kernel,
                         cudaFuncAttributeMaxDynamicSharedMemorySize, GEMM_SMEM);

    // 0) split inputs/weights into bf16 hi/lo
    const int n4_in = MROWS * HID / 4;
    const int n4_w  = PROJ * HID / 4;
    split_kernel<<<(n4_in + 255) / 256, 256>>>((const float4*)q,  0, n4_in);
    split_kernel<<<(n4_in + 255) / 256, 256>>>((const float4*)k,  1, n4_in);
    split_kernel<<<(n4_in + 255) / 256, 256>>>((const float4*)v,  2, n4_in);
    split_kernel<<<(n4_w  + 255) / 256, 256>>>((const float4*)Wq, 3, n4_w);
    split_kernel<<<(n4_w  + 255) / 256, 256>>>((const float4*)Wk, 4, n4_w);
    split_kernel<<<(n4_w  + 255) / 256, 256>>>((const float4*)Wv, 5, n4_w);
    split_kernel<<<(n4_w  + 255) / 256, 256>>>((const float4*)Wo, 6, n4_w);

    // 1) Q/K/V projections -> split bf16 heads (Q pre-scaled)
    {
        dim3 grid(PROJ / GBN, MROWS / GBM, 3);
        proj_tc_kernel<<<grid, GTHREADS, GEMM_SMEM>>>();
    }
    // 2) Tensor-core flash attention
    {
        dim3 grid(SEQ / 128, NHEAD, BSZ);
        attn_mma_kernel<<<grid, 256>>>();
    }
    // 3) Output projection
    {
        dim3 grid(HID / GBN, MROWS / GBM);
        out_tc_kernel<<<grid, GTHREADS, GEMM_SMEM>>>(out);
    }
}

// round 7
// speedup vs baseline: 2.6972x; 1.0928x over previous
#include <cuda_runtime.h>
#include <cuda_bf16.h>
#include <math_constants.h>
#include <cstdint>

// Problem constants
#define BSZ   2
#define SEQ   2048
#define HID   2048
#define NHEAD 32
#define HD    16
#define PROJ  512
#define MROWS (BSZ * SEQ)   // 4096
#define SCALE 0.125f
#define QPRE  (0.125f * 1.4426950408889634f)   // SCALE * log2(e)

// ---------------------------------------------------------------------------
// Persistent scratch (device globals — no allocation allowed)
// ---------------------------------------------------------------------------
__device__ __nv_bfloat16 g_IAh[(size_t)3 * MROWS * HID];
__device__ __nv_bfloat16 g_IAl[(size_t)3 * MROWS * HID];
__device__ __nv_bfloat16 g_WBh[(size_t)4 * PROJ * HID];
__device__ __nv_bfloat16 g_WBl[(size_t)4 * PROJ * HID];
__device__ __nv_bfloat16 g_Qh[MROWS * PROJ];
__device__ __nv_bfloat16 g_Ql[MROWS * PROJ];
__device__ __nv_bfloat16 g_Kh[MROWS * PROJ];
__device__ __nv_bfloat16 g_Kl[MROWS * PROJ];
__device__ __nv_bfloat16 g_Vh[MROWS * PROJ];
__device__ __nv_bfloat16 g_Vl[MROWS * PROJ];
__device__ __nv_bfloat16 g_AOh[MROWS * PROJ];
__device__ __nv_bfloat16 g_AOl[MROWS * PROJ];

// ---------------------------------------------------------------------------
// Helpers
// ---------------------------------------------------------------------------
__device__ __forceinline__ void split2(float x, float y, uint32_t& hi, uint32_t& lo) {
    __nv_bfloat16 hx = __float2bfloat16_rn(x);
    __nv_bfloat16 hy = __float2bfloat16_rn(y);
    float rx = x - __bfloat162float(hx);
    float ry = y - __bfloat162float(hy);
    __nv_bfloat16 lx = __float2bfloat16_rn(rx);
    __nv_bfloat16 ly = __float2bfloat16_rn(ry);
    hi = (uint32_t)__bfloat16_as_ushort(hx) | ((uint32_t)__bfloat16_as_ushort(hy) << 16);
    lo = (uint32_t)__bfloat16_as_ushort(lx) | ((uint32_t)__bfloat16_as_ushort(ly) << 16);
}

__device__ __forceinline__ void mma_bf16(float* c, const uint32_t* a, const uint32_t* b) {
    asm volatile(
        "mma.sync.aligned.m16n8k16.row.col.f32.bf16.bf16.f32 "
        "{%0,%1,%2,%3}, {%4,%5,%6,%7}, {%8,%9}, {%0,%1,%2,%3};"
        : "+f"(c[0]), "+f"(c[1]), "+f"(c[2]), "+f"(c[3])
        : "r"(a[0]), "r"(a[1]), "r"(a[2]), "r"(a[3]), "r"(b[0]), "r"(b[1]));
}

__device__ __forceinline__ void ldsm_x4(uint32_t addr, uint32_t& r0, uint32_t& r1,
                                        uint32_t& r2, uint32_t& r3) {
    asm volatile("ldmatrix.sync.aligned.m8n8.x4.shared.b16 {%0,%1,%2,%3}, [%4];"
                 : "=r"(r0), "=r"(r1), "=r"(r2), "=r"(r3) : "r"(addr));
}
__device__ __forceinline__ void ldsm_x2t(uint32_t addr, uint32_t& r0, uint32_t& r1) {
    asm volatile("ldmatrix.sync.aligned.m8n8.x2.trans.shared.b16 {%0,%1}, [%2];"
                 : "=r"(r0), "=r"(r1) : "r"(addr));
}

__device__ __forceinline__ uint32_t smem_u32(const void* p) {
    uint32_t a;
    asm("{ .reg .u64 t; cvta.to.shared.u64 t, %1; cvt.u32.u64 %0, t; }" : "=r"(a) : "l"(p));
    return a;
}

__device__ __forceinline__ void cpasync16(uint32_t dst, const void* src) {
    asm volatile("cp.async.cg.shared.global [%0], [%1], 16;" :: "r"(dst), "l"(src) : "memory");
}
__device__ __forceinline__ void cpcommit() {
    asm volatile("cp.async.commit_group;" ::: "memory");
}
template <int N>
__device__ __forceinline__ void cpwait() {
    asm volatile("cp.async.wait_group %0;" :: "n"(N) : "memory");
}

// ---------------------------------------------------------------------------
// One-time split pass
// ---------------------------------------------------------------------------
__global__ __launch_bounds__(256) void split_kernel(const float4* __restrict__ src,
                                                    int which, int n4) {
    int i = blockIdx.x * 256 + threadIdx.x;
    if (i >= n4) return;
    __nv_bfloat16 *dh, *dl;
    size_t off;
    if (which < 3) { dh = g_IAh; dl = g_IAl; off = (size_t)which * MROWS * HID; }
    else           { dh = g_WBh; dl = g_WBl; off = (size_t)(which - 3) * PROJ * HID; }
    float4 v = src[i];
    uint32_t h01, l01, h23, l23;
    split2(v.x, v.y, h01, l01);
    split2(v.z, v.w, h23, l23);
    ((uint2*)(dh + off))[i] = make_uint2(h01, h23);
    ((uint2*)(dl + off))[i] = make_uint2(l01, l23);
}

// ===========================================================================
// Split-bf16 tensor-core GEMM, cp.async double-buffered, ldmatrix fragments.
// ===========================================================================
#define GBM 128
#define GBN 128
#define GBK 32
#define GTHREADS 256
#define ROWB 80
#define TILEB (128 * ROWB)
#define OFF_AH 0
#define OFF_AL (1 * TILEB)
#define OFF_BH (2 * TILEB)
#define OFF_BL (3 * TILEB)
#define STAGE_B (4 * TILEB)
#define GEMM_SMEM (2 * STAGE_B)

__device__ __forceinline__ void tc_gemm_body(const __nv_bfloat16* __restrict__ Ahg,
                                             const __nv_bfloat16* __restrict__ Alg,
                                             const __nv_bfloat16* __restrict__ Bhg,
                                             const __nv_bfloat16* __restrict__ Blg,
                                             float* __restrict__ Cf,
                                             __nv_bfloat16* __restrict__ Chi,
                                             __nv_bfloat16* __restrict__ Clo,
                                             float pre,
                                             int K, int N) {
    extern __shared__ char smem[];
    const uint32_t sb = smem_u32(smem);

    const int tid = threadIdx.x;
    const int wid = tid >> 5;
    const int lane = tid & 31;
    const int wm = wid >> 2;
    const int wn = wid & 3;
    const int gid = lane >> 2;
    const int tig = lane & 3;

    const int m0 = blockIdx.y * GBM;
    const int n0 = blockIdx.x * GBN;
    const int nc = K / GBK;

    const int crow0 = (tid + 0)   >> 2, cch0 = (tid + 0)   & 3;
    const int crow1 = (tid + 256) >> 2, cch1 = (tid + 256) & 3;

    // per-lane ldmatrix base offsets (bytes within a tile buffer)
    const uint32_t a_lm = (uint32_t)((wm * 64 + (lane & 15)) * ROWB + (lane >> 4) * 16);
    const uint32_t b_lm = (uint32_t)((wn * 32 + (lane & 7) + ((lane >> 4) & 1) * 8) * ROWB
                                     + ((lane >> 3) & 1) * 16);

    float acc[4][4][4];
#pragma unroll
    for (int mt = 0; mt < 4; mt++)
#pragma unroll
        for (int nt = 0; nt < 4; nt++)
#pragma unroll
            for (int r = 0; r < 4; r++) acc[mt][nt][r] = 0.f;

    auto issue_stage = [&](int i) {
        const int s = i & 1;
        const int k0 = i * GBK;
        const uint32_t st = sb + s * STAGE_B;
        {
            const uint32_t d = (uint32_t)(crow0 * ROWB + cch0 * 16);
            const size_t ga = (size_t)(m0 + crow0) * K + k0 + cch0 * 8;
            const size_t gb = (size_t)(n0 + crow0) * K + k0 + cch0 * 8;
            cpasync16(st + OFF_AH + d, Ahg + ga);
            cpasync16(st + OFF_AL + d, Alg + ga);
            cpasync16(st + OFF_BH + d, Bhg + gb);
            cpasync16(st + OFF_BL + d, Blg + gb);
        }
        {
            const uint32_t d = (uint32_t)(crow1 * ROWB + cch1 * 16);
            const size_t ga = (size_t)(m0 + crow1) * K + k0 + cch1 * 8;
            const size_t gb = (size_t)(n0 + crow1) * K + k0 + cch1 * 8;
            cpasync16(st + OFF_AH + d, Ahg + ga);
            cpasync16(st + OFF_AL + d, Alg + ga);
            cpasync16(st + OFF_BH + d, Bhg + gb);
            cpasync16(st + OFF_BL + d, Blg + gb);
        }
    };

    issue_stage(0);
    cpcommit();

    for (int i = 0; i < nc; i++) {
        if (i + 1 < nc) {
            issue_stage(i + 1);
            cpcommit();
            cpwait<1>();
        } else {
            cpwait<0>();
        }
        __syncthreads();

        const uint32_t st = sb + (i & 1) * STAGE_B;

#pragma unroll
        for (int ks = 0; ks < 2; ks++) {
            const uint32_t koff = ks * 32;     // 16 bf16 = 32 bytes
            // B fragments: 2 n-halves x (hi,lo), each one ldmatrix.x4
            uint32_t bh[4][2], bl[4][2];
            ldsm_x4(st + OFF_BH + b_lm + koff,
                    bh[0][0], bh[0][1], bh[1][0], bh[1][1]);
            ldsm_x4(st + OFF_BH + b_lm + 16 * ROWB + koff,
                    bh[2][0], bh[2][1], bh[3][0], bh[3][1]);
            ldsm_x4(st + OFF_BL + b_lm + koff,
                    bl[0][0], bl[0][1], bl[1][0], bl[1][1]);
            ldsm_x4(st + OFF_BL + b_lm + 16 * ROWB + koff,
                    bl[2][0], bl[2][1], bl[3][0], bl[3][1]);
#pragma unroll
            for (int mt = 0; mt < 4; mt++) {
                uint32_t ah[4], al[4];
                ldsm_x4(st + OFF_AH + a_lm + mt * 16 * ROWB + koff,
                        ah[0], ah[1], ah[2], ah[3]);
                ldsm_x4(st + OFF_AL + a_lm + mt * 16 * ROWB + koff,
                        al[0], al[1], al[2], al[3]);
#pragma unroll
                for (int nt = 0; nt < 4; nt++) {
                    mma_bf16(acc[mt][nt], ah, bh[nt]);
                    mma_bf16(acc[mt][nt], ah, bl[nt]);
                    mma_bf16(acc[mt][nt], al, bh[nt]);
                }
            }
        }
        __syncthreads();
    }

#pragma unroll
    for (int mt = 0; mt < 4; mt++) {
#pragma unroll
        for (int nt = 0; nt < 4; nt++) {
            const int m = m0 + wm * 64 + mt * 16 + gid;
            const int n = n0 + wn * 32 + nt * 8 + 2 * tig;
            if (Cf) {
                *(float2*)&Cf[(size_t)m * N + n] = make_float2(acc[mt][nt][0], acc[mt][nt][1]);
                *(float2*)&Cf[(size_t)(m + 8) * N + n] = make_float2(acc[mt][nt][2], acc[mt][nt][3]);
            } else {
                uint32_t hi, lo;
                split2(acc[mt][nt][0] * pre, acc[mt][nt][1] * pre, hi, lo);
                *(uint32_t*)&Chi[(size_t)m * N + n] = hi;
                *(uint32_t*)&Clo[(size_t)m * N + n] = lo;
                split2(acc[mt][nt][2] * pre, acc[mt][nt][3] * pre, hi, lo);
                *(uint32_t*)&Chi[(size_t)(m + 8) * N + n] = hi;
                *(uint32_t*)&Clo[(size_t)(m + 8) * N + n] = lo;
            }
        }
    }
}

__global__ __launch_bounds__(GTHREADS, 2)
void proj_tc_kernel() {
    const size_t za = (size_t)blockIdx.z * MROWS * HID;
    const size_t zw = (size_t)blockIdx.z * PROJ * HID;
    __nv_bfloat16 *Chi, *Clo;
    float pre = 1.f;
    if (blockIdx.z == 0)      { Chi = g_Qh; Clo = g_Ql; pre = QPRE; }
    else if (blockIdx.z == 1) { Chi = g_Kh; Clo = g_Kl; }
    else                      { Chi = g_Vh; Clo = g_Vl; }
    tc_gemm_body(g_IAh + za, g_IAl + za, g_WBh + zw, g_WBl + zw,
                 nullptr, Chi, Clo, pre, HID, PROJ);
}

__global__ __launch_bounds__(GTHREADS, 2)
void out_tc_kernel(float* __restrict__ out) {
    const size_t zw = (size_t)3 * PROJ * HID;
    tc_gemm_body(g_AOh, g_AOl, g_WBh + zw, g_WBl + zw,
                 out, nullptr, nullptr, 1.f, PROJ, HID);
}

// ===========================================================================
// Tensor-core flash attention with ldmatrix (incl. .trans for V).
// Block = 256 threads (8 warps) x 128 query rows; warp owns 16 rows.
// K/V staged row-major [key][16d], rows padded to 24 elems (48 B) so every
// ldmatrix phase hits 8 disjoint bank quads.
// ===========================================================================
#define KVROW 24
#define KVROWB 48

__global__ __launch_bounds__(256, 2) void attn_mma_kernel() {
    __shared__ __align__(16) __nv_bfloat16 Kh[128][KVROW];
    __shared__ __align__(16) __nv_bfloat16 Kl[128][KVROW];
    __shared__ __align__(16) __nv_bfloat16 Vh[128][KVROW];
    __shared__ __align__(16) __nv_bfloat16 Vl[128][KVROW];

    const int tid = threadIdx.x;
    const int wid = tid >> 5;
    const int lane = tid & 31;
    const int gid = lane >> 2;
    const int tig = lane & 3;
    const int h = blockIdx.y;
    const int b = blockIdx.z;
    const int q0 = blockIdx.x * 128;

    const uint32_t kh_b = smem_u32(&Kh[0][0]);
    const uint32_t kl_b = smem_u32(&Kl[0][0]);
    const uint32_t vh_b = smem_u32(&Vh[0][0]);
    const uint32_t vl_b = smem_u32(&Vl[0][0]);

    // per-lane ldmatrix offsets
    const uint32_t k_lm = (uint32_t)(((lane & 7) + ((lane >> 4) & 1) * 8) * KVROWB
                                     + ((lane >> 3) & 1) * 16);
    const uint32_t v_lm = (uint32_t)((lane & 15) * KVROWB);

    // Q fragments (persistent, hi/lo)
    const size_t qrow = (size_t)(b * SEQ + q0 + wid * 16);
    uint32_t qh[4], ql[4];
    {
        const __nv_bfloat16* Q0 = g_Qh + (qrow + gid) * PROJ + h * HD;
        const __nv_bfloat16* Q8 = g_Qh + (qrow + gid + 8) * PROJ + h * HD;
        qh[0] = *(const uint32_t*)(Q0 + 2 * tig);
        qh[1] = *(const uint32_t*)(Q8 + 2 * tig);
        qh[2] = *(const uint32_t*)(Q0 + 2 * tig + 8);
        qh[3] = *(const uint32_t*)(Q8 + 2 * tig + 8);
        const __nv_bfloat16* q0l = g_Ql + (qrow + gid) * PROJ + h * HD;
        const __nv_bfloat16* q8l = g_Ql + (qrow + gid + 8) * PROJ + h * HD;
        ql[0] = *(const uint32_t*)(q0l + 2 * tig);
        ql[1] = *(const uint32_t*)(q8l + 2 * tig);
        ql[2] = *(const uint32_t*)(q0l + 2 * tig + 8);
        ql[3] = *(const uint32_t*)(q8l + 2 * tig + 8);
    }

    float m0v = -CUDART_INF_F, m1v = -CUDART_INF_F;
    float l0 = 0.f, l1 = 0.f;
    float o[2][4];
#pragma unroll
    for (int a = 0; a < 2; a++)
#pragma unroll
        for (int r = 0; r < 4; r++) o[a][r] = 0.f;

    for (int kt = 0; kt < SEQ; kt += 128) {
        __syncthreads();
        // stage K and V: thread t stages half-row (t>>1, half t&1) of all 4 arrays
        {
            const int srow = tid >> 1, shalf = tid & 1;
            const size_t src = ((size_t)(b * SEQ + kt) + srow) * PROJ + h * HD + shalf * 8;
            *(uint4*)&Kh[srow][shalf * 8] = *(const uint4*)(g_Kh + src);
            *(uint4*)&Kl[srow][shalf * 8] = *(const uint4*)(g_Kl + src);
            *(uint4*)&Vh[srow][shalf * 8] = *(const uint4*)(g_Vh + src);
            *(uint4*)&Vl[srow][shalf * 8] = *(const uint4*)(g_Vl + src);
        }
        __syncthreads();

        // scores: 8 pairs of n-tiles, B fragments via ldmatrix.x4
        float sc[16][4];
#pragma unroll
        for (int p = 0; p < 8; p++) {
            uint32_t bh[2][2], bl[2][2];
            ldsm_x4(kh_b + k_lm + p * 16 * KVROWB, bh[0][0], bh[0][1], bh[1][0], bh[1][1]);
            ldsm_x4(kl_b + k_lm + p * 16 * KVROWB, bl[0][0], bl[0][1], bl[1][0], bl[1][1]);
#pragma unroll
            for (int q = 0; q < 2; q++) {
                const int nt = 2 * p + q;
                sc[nt][0] = sc[nt][1] = sc[nt][2] = sc[nt][3] = 0.f;
                mma_bf16(sc[nt], qh, bh[q]);
                mma_bf16(sc[nt], qh, bl[q]);
                mma_bf16(sc[nt], ql, bh[q]);
            }
        }

        // row max
        float mx0 = sc[0][0], mx1 = sc[0][2];
#pragma unroll
        for (int nt = 0; nt < 16; nt++) {
            mx0 = fmaxf(mx0, fmaxf(sc[nt][0], sc[nt][1]));
            mx1 = fmaxf(mx1, fmaxf(sc[nt][2], sc[nt][3]));
        }
        mx0 = fmaxf(mx0, __shfl_xor_sync(0xffffffffu, mx0, 1));
        mx0 = fmaxf(mx0, __shfl_xor_sync(0xffffffffu, mx0, 2));
        mx1 = fmaxf(mx1, __shfl_xor_sync(0xffffffffu, mx1, 1));
        mx1 = fmaxf(mx1, __shfl_xor_sync(0xffffffffu, mx1, 2));

        const float mn0 = fmaxf(m0v, mx0);
        const float mn1 = fmaxf(m1v, mx1);
        const float al0 = exp2f(m0v - mn0);
        const float al1 = exp2f(m1v - mn1);
        m0v = mn0; m1v = mn1;
        l0 *= al0; l1 *= al1;
#pragma unroll
        for (int a = 0; a < 2; a++) {
            o[a][0] *= al0; o[a][1] *= al0;
            o[a][2] *= al1; o[a][3] *= al1;
        }

        // P (exp2) + PV mma; V B-fragments via ldmatrix.x2.trans
        float s0 = 0.f, s1 = 0.f;
#pragma unroll
        for (int kc = 0; kc < 8; kc++) {
            float p[8];
            p[0] = exp2f(sc[2 * kc][0] - m0v);
            p[1] = exp2f(sc[2 * kc][1] - m0v);
            p[2] = exp2f(sc[2 * kc][2] - m1v);
            p[3] = exp2f(sc[2 * kc][3] - m1v);
            p[4] = exp2f(sc[2 * kc + 1][0] - m0v);
            p[5] = exp2f(sc[2 * kc + 1][1] - m0v);
            p[6] = exp2f(sc[2 * kc + 1][2] - m1v);
            p[7] = exp2f(sc[2 * kc + 1][3] - m1v);
            s0 += p[0] + p[1] + p[4] + p[5];
            s1 += p[2] + p[3] + p[6] + p[7];

            uint32_t ah[4], al[4];
#pragma unroll
            for (int j = 0; j < 4; j++) {
                __nv_bfloat162 hv = __floats2bfloat162_rn(p[2 * j], p[2 * j + 1]);
                ah[j] = *(uint32_t*)&hv;
                float rlo = p[2 * j] - __bfloat162float(hv.x);
                float rhi = p[2 * j + 1] - __bfloat162float(hv.y);
                __nv_bfloat162 lv = __floats2bfloat162_rn(rlo, rhi);
                al[j] = *(uint32_t*)&lv;
            }
#pragma unroll
            for (int nt2 = 0; nt2 < 2; nt2++) {
                uint32_t bvh[2], bvl[2];
                ldsm_x2t(vh_b + v_lm + kc * 16 * KVROWB + nt2 * 16, bvh[0], bvh[1]);
                ldsm_x2t(vl_b + v_lm + kc * 16 * KVROWB + nt2 * 16, bvl[0], bvl[1]);
                mma_bf16(o[nt2], ah, bvh);
                mma_bf16(o[nt2], ah, bvl);
                mma_bf16(o[nt2], al, bvh);
            }
        }
        s0 += __shfl_xor_sync(0xffffffffu, s0, 1);
        s0 += __shfl_xor_sync(0xffffffffu, s0, 2);
        s1 += __shfl_xor_sync(0xffffffffu, s1, 1);
        s1 += __shfl_xor_sync(0xffffffffu, s1, 2);
        l0 += s0; l1 += s1;
    }

    // epilogue
    const float i0 = 1.f / l0;
    const float i1 = 1.f / l1;
    const size_t rA = (qrow + gid) * PROJ + h * HD;
    const size_t rB = (qrow + gid + 8) * PROJ + h * HD;
#pragma unroll
    for (int nt2 = 0; nt2 < 2; nt2++) {
        uint32_t hi, lo;
        split2(o[nt2][0] * i0, o[nt2][1] * i0, hi, lo);
        *(uint32_t*)&g_AOh[rA + nt2 * 8 + 2 * tig] = hi;
        *(uint32_t*)&g_AOl[rA + nt2 * 8 + 2 * tig] = lo;
        split2(o[nt2][2] * i1, o[nt2][3] * i1, hi, lo);
        *(uint32_t*)&g_AOh[rB + nt2 * 8 + 2 * tig] = hi;
        *(uint32_t*)&g_AOl[rB + nt2 * 8 + 2 * tig] = lo;
    }
}

// ---------------------------------------------------------------------------
extern "C" void kernel_launch(void* const* d_in, const int* in_sizes, int n_in,
                              void* d_out, int out_size) {
    const float* q  = (const float*)d_in[0];
    const float* k  = (const float*)d_in[1];
    const float* v  = (const float*)d_in[2];
    const float* Wq = (const float*)d_in[3];
    const float* Wk = (const float*)d_in[4];
    const float* Wv = (const float*)d_in[5];
    const float* Wo = (const float*)d_in[6];
    float* out = (float*)d_out;

    cudaFuncSetAttribute(proj_tc_kernel,
                         cudaFuncAttributeMaxDynamicSharedMemorySize, GEMM_SMEM);
    cudaFuncSetAttribute(out_tc_kernel,
                         cudaFuncAttributeMaxDynamicSharedMemorySize, GEMM_SMEM);

    const int n4_in = MROWS * HID / 4;
    const int n4_w  = PROJ * HID / 4;
    split_kernel<<<(n4_in + 255) / 256, 256>>>((const float4*)q,  0, n4_in);
    split_kernel<<<(n4_in + 255) / 256, 256>>>((const float4*)k,  1, n4_in);
    split_kernel<<<(n4_in + 255) / 256, 256>>>((const float4*)v,  2, n4_in);
    split_kernel<<<(n4_w  + 255) / 256, 256>>>((const float4*)Wq, 3, n4_w);
    split_kernel<<<(n4_w  + 255) / 256, 256>>>((const float4*)Wk, 4, n4_w);
    split_kernel<<<(n4_w  + 255) / 256, 256>>>((const float4*)Wv, 5, n4_w);
    split_kernel<<<(n4_w  + 255) / 256, 256>>>((const float4*)Wo, 6, n4_w);

    {
        dim3 grid(PROJ / GBN, MROWS / GBM, 3);
        proj_tc_kernel<<<grid, GTHREADS, GEMM_SMEM>>>();
    }
    {
        dim3 grid(SEQ / 128, NHEAD, BSZ);
        attn_mma_kernel<<<grid, 256>>>();
    }
    {
        dim3 grid(HID / GBN, MROWS / GBM);
        out_tc_kernel<<<grid, GTHREADS, GEMM_SMEM>>>(out);
    }
}